// round 11
// baseline (speedup 1.0000x reference)
#include <cuda_runtime.h>
#include <cstdint>

using ull = unsigned long long;

// ---------- packed f32x2 helpers (pack axis = channel c) ----------
__device__ __forceinline__ ull f2add(ull a, ull b) {
    ull d; asm("add.rn.f32x2 %0, %1, %2;" : "=l"(d) : "l"(a), "l"(b)); return d;
}
__device__ __forceinline__ ull f2mul(ull a, ull b) {
    ull d; asm("mul.rn.f32x2 %0, %1, %2;" : "=l"(d) : "l"(a), "l"(b)); return d;
}
__device__ __forceinline__ ull f2fma(ull a, ull b, ull c) {
    ull d; asm("fma.rn.f32x2 %0, %1, %2, %3;" : "=l"(d) : "l"(a), "l"(b), "l"(c)); return d;
}
__device__ __forceinline__ ull f2relu(ull p) {
    ull d;
    asm("{ .reg .f32 lo, hi;\n\t"
        "  mov.b64 {lo, hi}, %1;\n\t"
        "  max.f32 lo, lo, 0f00000000;\n\t"
        "  max.f32 hi, hi, 0f00000000;\n\t"
        "  mov.b64 %0, {lo, hi}; }" : "=l"(d) : "l"(p));
    return d;
}
__device__ __forceinline__ float f2hadd(ull p) {
    float a, b; asm("mov.b64 {%0, %1}, %2;" : "=f"(a), "=f"(b) : "l"(p));
    return a + b;
}
__device__ __forceinline__ ull f2pack(float a, float b) {
    ull r; asm("mov.b64 %0, {%1, %2};" : "=l"(r) : "f"(a), "f"(b)); return r;
}
__device__ __forceinline__ float sigm(float x) { return 1.0f / (1.0f + __expf(-x)); }

// u/v exchange layout (floats): addr = g*168 + phase*20 + c.
// 168 mod 32 = 8 -> 4 per-warp g-bases hit bank quads 0/8/16/24: LDS128 1 wavefront.
#define G_STRIDE 168

// 5 blocks/SM (96-reg cap): C=2 chunking + up reloaded per chunk keeps live set ~90.
__global__ __launch_bounds__(128, 5)
void frap_kernel(const float* __restrict__ states,
                 const int*   __restrict__ comp_mask,
                 const int*   __restrict__ phase_pairs,
                 const float* __restrict__ p_w,
                 const float* __restrict__ d_w,  const float* __restrict__ d_b,
                 const float* __restrict__ le_w, const float* __restrict__ le_b,
                 const float* __restrict__ lc_w, const float* __restrict__ lc_b,
                 const float* __restrict__ rel_w,
                 const float* __restrict__ rc_w, const float* __restrict__ rc_b,
                 const float* __restrict__ h_w,  const float* __restrict__ h_b,
                 const float* __restrict__ bm_w, const float* __restrict__ bm_b,
                 float* __restrict__ out, int B)
{
    __shared__ __align__(16) float s_lcA[20][16];     // lc_w[:, 0:16]
    __shared__ __align__(16) float s_lcB[20][16];     // lc_w[:, 16:32]
    __shared__ __align__(16) float s_hw[20][20];      // natural c-pairs for f32x2
    __shared__ __align__(16) float s_rel[8 * 8 * 20]; // [q][i][20]; zero row when q==i
    __shared__ float s_leD[4][16];
    __shared__ float s_lcb[20], s_bmw[20], s_dw[4], s_db[4];
    __shared__ ull   s_hb2[20];                       // packed (h_b[o], 0)
    __shared__ float s_base[2][16];
    __shared__ int   s_pp[16];
    __shared__ float s_bmb, s_corr;                   // corr = sum_o bm[o]*relu(h_b[o])
    __shared__ __align__(16) float s_u[16 * G_STRIDE];
    __shared__ __align__(16) float s_v[16 * G_STRIDE];

    const int tid = threadIdx.x;

    // ---------------- block-local precompute ----------------
    for (int idx = tid; idx < 320; idx += 128) {
        int o = idx >> 4, c = idx & 15;
        s_lcA[o][c] = lc_w[o * 32 + c];
        s_lcB[o][c] = lc_w[o * 32 + 16 + c];
    }
    for (int idx = tid; idx < 400; idx += 128) {
        int o = idx / 20, c = idx % 20;
        s_hw[o][c] = h_w[o * 20 + c];
    }
    // s_rel[q][i][o]: rel row for pair (i, j=q); zero when q==i (dummy lane, corrected)
    for (int idx = tid; idx < 1280; idx += 128) {
        int qi = idx / 20, o = idx % 20;
        int q = qi >> 3, i = qi & 7;
        float val = 0.0f;
        if (q != i) {
            int cm = i * 7 + (q > i ? q - 1 : q);
            int e = comp_mask[cm];
            float acc = rc_b[o];
            #pragma unroll
            for (int c4 = 0; c4 < 4; c4++)
                acc += fmaxf(rel_w[e * 4 + c4], 0.0f) * rc_w[o * 4 + c4];
            val = fmaxf(acc, 0.0f);
        }
        s_rel[qi * 20 + o] = val;
    }
    for (int idx = tid; idx < 64; idx += 128) {
        int k = idx >> 4, c = idx & 15;
        s_leD[k][c] = le_w[(4 + k) * 16 + c];
    }
    if (tid < 32) {
        int e = tid >> 4, c = tid & 15;
        float a = le_b[c];
        #pragma unroll
        for (int k = 0; k < 4; k++) a += sigm(p_w[e * 4 + k]) * le_w[k * 16 + c];
        s_base[e][c] = a;
    }
    if (tid < 20) {
        s_lcb[tid] = lc_b[tid];
        s_bmw[tid] = bm_w[tid];
        s_hb2[tid] = f2pack(h_b[tid], 0.0f);
    }
    if (tid < 4) { s_dw[tid] = d_w[tid]; s_db[tid] = d_b[tid]; }
    if (tid < 16) s_pp[tid] = phase_pairs[tid];
    if (tid == 0) {
        s_bmb = bm_b[0];
        float corr = 0.0f;
        #pragma unroll
        for (int o = 0; o < 20; o++) corr += bm_w[o] * fmaxf(h_b[o], 0.0f);
        s_corr = corr;
    }
    __syncthreads();

    // ---------------- per-thread: (batch elem b) x (output phase i) ----------------
    const int g = tid >> 3;
    const int i = tid & 7;
    const int b = blockIdx.x * 16 + g;
    const bool valid = (b < B);
    const float* st = states + (valid ? b : 0) * 13;

    const int a  = (int)st[0];
    const int pa0 = s_pp[a * 2], pa1 = s_pp[a * 2 + 1];
    const int mA  = s_pp[i * 2], mB  = s_pp[i * 2 + 1];

    // ---------- stage 0: pairs[i] = lane[mA] + lane[mB] ----------
    float pairs[16];
    #pragma unroll
    for (int c = 0; c < 16; c++) pairs[c] = 0.0f;

    #pragma unroll
    for (int t = 0; t < 2; t++) {
        const int m = (t == 0) ? mA : mB;
        const float dm = st[1 + m];
        float de[4];
        #pragma unroll
        for (int k = 0; k < 4; k++) de[k] = sigm(fmaf(dm, s_dw[k], s_db[k]));
        const int e = (m == pa0 || m == pa1) ? 1 : 0;
        #pragma unroll
        for (int c = 0; c < 16; c++) {
            float acc = s_base[e][c];
            #pragma unroll
            for (int k = 0; k < 4; k++) acc = fmaf(de[k], s_leD[k][c], acc);
            pairs[c] += fmaxf(acc, 0.0f);
        }
    }

    // ---------- stage 1: u = lcA@pairs + lc_b; v = lcB@pairs -> shared ----------
    const int slot = g * G_STRIDE + i * 20;
    {
        float4* u4p = reinterpret_cast<float4*>(&s_u[slot]);
        float4* v4p = reinterpret_cast<float4*>(&s_v[slot]);
        #pragma unroll 1
        for (int ob = 0; ob < 5; ob++) {
            float ur[4], vr[4];
            #pragma unroll
            for (int oi = 0; oi < 4; oi++) {
                const int o = ob * 4 + oi;
                const float4* wa = reinterpret_cast<const float4*>(&s_lcA[o][0]);
                const float4* wb = reinterpret_cast<const float4*>(&s_lcB[o][0]);
                float au = s_lcb[o], av = 0.0f;
                #pragma unroll
                for (int c4 = 0; c4 < 4; c4++) {
                    float4 A = wa[c4], Bv = wb[c4];
                    au = fmaf(A.x,  pairs[c4 * 4 + 0], au);
                    av = fmaf(Bv.x, pairs[c4 * 4 + 0], av);
                    au = fmaf(A.y,  pairs[c4 * 4 + 1], au);
                    av = fmaf(Bv.y, pairs[c4 * 4 + 1], av);
                    au = fmaf(A.z,  pairs[c4 * 4 + 2], au);
                    av = fmaf(Bv.z, pairs[c4 * 4 + 2], av);
                    au = fmaf(A.w,  pairs[c4 * 4 + 3], au);
                    av = fmaf(Bv.w, pairs[c4 * 4 + 3], av);
                }
                ur[oi] = au; vr[oi] = av;
            }
            u4p[ob] = make_float4(ur[0], ur[1], ur[2], ur[3]);
            v4p[ob] = make_float4(vr[0], vr[1], vr[2], vr[3]);
        }
    }
    __syncthreads();

    // ---------- stage 2: packed-by-c f32x2, q chunked by 2; up reloaded per chunk ----------
    const int gv = g * G_STRIDE;
    float acc = 0.0f;

    #pragma unroll 1
    for (int qc = 0; qc < 4; qc++) {
        const int q0 = 2 * qc, q1 = q0 + 1;
        ull c0[10], c1[10];
        {
            // reload u per chunk: 5 LDS128 buys 20 persistent registers
            ull up[10];
            const ulonglong2* uu = reinterpret_cast<const ulonglong2*>(&s_u[slot]);
            #pragma unroll
            for (int k = 0; k < 5; k++) { ulonglong2 t = uu[k]; up[2*k] = t.x; up[2*k+1] = t.y; }

            const ulonglong2* v0 = reinterpret_cast<const ulonglong2*>(&s_v[gv + q0 * 20]);
            const ulonglong2* r0 = reinterpret_cast<const ulonglong2*>(&s_rel[(q0 * 8 + i) * 20]);
            const ulonglong2* v1 = reinterpret_cast<const ulonglong2*>(&s_v[gv + q1 * 20]);
            const ulonglong2* r1 = reinterpret_cast<const ulonglong2*>(&s_rel[(q1 * 8 + i) * 20]);
            #pragma unroll
            for (int k = 0; k < 5; k++) {
                ulonglong2 va = v0[k], ra = r0[k];
                ulonglong2 vb = v1[k], rb = r1[k];
                c0[2*k+0] = f2mul(f2relu(f2add(up[2*k+0], va.x)), ra.x);
                c0[2*k+1] = f2mul(f2relu(f2add(up[2*k+1], va.y)), ra.y);
                c1[2*k+0] = f2mul(f2relu(f2add(up[2*k+0], vb.x)), rb.x);
                c1[2*k+1] = f2mul(f2relu(f2add(up[2*k+1], vb.y)), rb.y);
            }
        }

        #pragma unroll 2
        for (int o = 0; o < 20; o++) {
            const ulonglong2* w2 = reinterpret_cast<const ulonglong2*>(&s_hw[o][0]);
            ull h0 = s_hb2[o], h1 = h0;
            #pragma unroll
            for (int k = 0; k < 5; k++) {
                ulonglong2 w = w2[k];
                h0 = f2fma(w.x, c0[2*k+0], h0);
                h1 = f2fma(w.x, c1[2*k+0], h1);
                h0 = f2fma(w.y, c0[2*k+1], h0);
                h1 = f2fma(w.y, c1[2*k+1], h1);
            }
            const float bw = s_bmw[o];
            acc = fmaf(bw, fmaxf(f2hadd(h0), 0.0f), acc);
            acc = fmaf(bw, fmaxf(f2hadd(h1), 0.0f), acc);
        }
    }

    // subtract dummy-q contribution (comb=0 -> h=h_b), add 7x bm bias
    if (valid) out[b * 8 + i] = acc - s_corr + 7.0f * s_bmb;
}

extern "C" void kernel_launch(void* const* d_in, const int* in_sizes, int n_in,
                              void* d_out, int out_size)
{
    const float* states      = (const float*)d_in[0];
    const int*   comp_mask   = (const int*)  d_in[1];
    const int*   phase_pairs = (const int*)  d_in[2];
    const float* p_w  = (const float*)d_in[3];
    const float* d_w  = (const float*)d_in[4];
    const float* d_b  = (const float*)d_in[5];
    const float* le_w = (const float*)d_in[6];
    const float* le_b = (const float*)d_in[7];
    const float* lc_w = (const float*)d_in[8];
    const float* lc_b = (const float*)d_in[9];
    const float* rel_w = (const float*)d_in[10];
    const float* rc_w  = (const float*)d_in[11];
    const float* rc_b  = (const float*)d_in[12];
    const float* h_w   = (const float*)d_in[13];
    const float* h_b   = (const float*)d_in[14];
    const float* bm_w  = (const float*)d_in[15];
    const float* bm_b  = (const float*)d_in[16];

    const int B = in_sizes[0] / 13;           // states is [B, 1 + 12]
    const int blocks = (B + 15) / 16;         // 16 batch elems x 8 phases per 128-thread block

    frap_kernel<<<blocks, 128>>>(states, comp_mask, phase_pairs,
                                 p_w, d_w, d_b, le_w, le_b, lc_w, lc_b,
                                 rel_w, rc_w, rc_b, h_w, h_b, bm_w, bm_b,
                                 (float*)d_out, B);
}

// round 12
// speedup vs baseline: 1.0478x; 1.0478x over previous
#include <cuda_runtime.h>
#include <cstdint>

using ull = unsigned long long;

// ---------- packed f32x2 helpers (pack axis = channel c) ----------
__device__ __forceinline__ ull f2fma(ull a, ull b, ull c) {
    ull d; asm("fma.rn.f32x2 %0, %1, %2, %3;" : "=l"(d) : "l"(a), "l"(b), "l"(c)); return d;
}
__device__ __forceinline__ float f2hadd(ull p) {
    float a, b; asm("mov.b64 {%0, %1}, %2;" : "=f"(a), "=f"(b) : "l"(p));
    return a + b;
}
__device__ __forceinline__ ull f2pack(float a, float b) {
    ull r; asm("mov.b64 %0, {%1, %2};" : "=l"(r) : "f"(a), "f"(b)); return r;
}
__device__ __forceinline__ float sigm(float x) { return 1.0f / (1.0f + __expf(-x)); }

// u/v exchange layout (floats): addr = g*168 + phase*20 + c.
// 168 mod 32 = 8 -> 4 per-warp g-bases hit bank quads 0/8/16/24: LDS128 1 wavefront.
#define G_STRIDE 168

__global__ __launch_bounds__(128, 4)
void frap_kernel(const float* __restrict__ states,
                 const int*   __restrict__ comp_mask,
                 const int*   __restrict__ phase_pairs,
                 const float* __restrict__ p_w,
                 const float* __restrict__ d_w,  const float* __restrict__ d_b,
                 const float* __restrict__ le_w, const float* __restrict__ le_b,
                 const float* __restrict__ lc_w, const float* __restrict__ lc_b,
                 const float* __restrict__ rel_w,
                 const float* __restrict__ rc_w, const float* __restrict__ rc_b,
                 const float* __restrict__ h_w,  const float* __restrict__ h_b,
                 const float* __restrict__ bm_w, const float* __restrict__ bm_b,
                 float* __restrict__ out, int B)
{
    __shared__ __align__(16) float s_lcA[20][16];     // lc_w[:, 0:16]
    __shared__ __align__(16) float s_lcB[20][16];     // lc_w[:, 16:32]
    __shared__ __align__(16) float s_hw[20][20];      // natural c-pairs for f32x2
    __shared__ __align__(16) float s_rel[8 * 8 * 20]; // [q][i][20]; zero row when q==i
    __shared__ float s_leD[4][16];
    __shared__ float s_lcb[20], s_bmw[20], s_dw[4], s_db[4];
    __shared__ ull   s_hb2[20];                       // packed (h_b[o], 0)
    __shared__ float s_base[2][16];
    __shared__ int   s_pp[16];
    __shared__ float s_bmb, s_corr;                   // corr = sum_o bm[o]*relu(h_b[o])
    __shared__ __align__(16) float s_u[16 * G_STRIDE];
    __shared__ __align__(16) float s_v[16 * G_STRIDE];

    const int tid = threadIdx.x;

    // ---------------- block-local precompute ----------------
    for (int idx = tid; idx < 320; idx += 128) {
        int o = idx >> 4, c = idx & 15;
        s_lcA[o][c] = lc_w[o * 32 + c];
        s_lcB[o][c] = lc_w[o * 32 + 16 + c];
    }
    for (int idx = tid; idx < 400; idx += 128) {
        int o = idx / 20, c = idx % 20;
        s_hw[o][c] = h_w[o * 20 + c];
    }
    // s_rel[q][i][o]: rel row for pair (i, j=q); zero when q==i (dummy lane, corrected)
    for (int idx = tid; idx < 1280; idx += 128) {
        int qi = idx / 20, o = idx % 20;
        int q = qi >> 3, i = qi & 7;
        float val = 0.0f;
        if (q != i) {
            int cm = i * 7 + (q > i ? q - 1 : q);
            int e = comp_mask[cm];
            float acc = rc_b[o];
            #pragma unroll
            for (int c4 = 0; c4 < 4; c4++)
                acc += fmaxf(rel_w[e * 4 + c4], 0.0f) * rc_w[o * 4 + c4];
            val = fmaxf(acc, 0.0f);
        }
        s_rel[qi * 20 + o] = val;
    }
    for (int idx = tid; idx < 64; idx += 128) {
        int k = idx >> 4, c = idx & 15;
        s_leD[k][c] = le_w[(4 + k) * 16 + c];
    }
    if (tid < 32) {
        int e = tid >> 4, c = tid & 15;
        float a = le_b[c];
        #pragma unroll
        for (int k = 0; k < 4; k++) a += sigm(p_w[e * 4 + k]) * le_w[k * 16 + c];
        s_base[e][c] = a;
    }
    if (tid < 20) {
        s_lcb[tid] = lc_b[tid];
        s_bmw[tid] = bm_w[tid];
        s_hb2[tid] = f2pack(h_b[tid], 0.0f);
    }
    if (tid < 4) { s_dw[tid] = d_w[tid]; s_db[tid] = d_b[tid]; }
    if (tid < 16) s_pp[tid] = phase_pairs[tid];
    if (tid == 0) {
        s_bmb = bm_b[0];
        float corr = 0.0f;
        #pragma unroll
        for (int o = 0; o < 20; o++) corr += bm_w[o] * fmaxf(h_b[o], 0.0f);
        s_corr = corr;
    }
    __syncthreads();

    // ---------------- per-thread: (batch elem b) x (output phase i) ----------------
    const int g = tid >> 3;
    const int i = tid & 7;
    const int b = blockIdx.x * 16 + g;
    const bool valid = (b < B);
    const float* st = states + (valid ? b : 0) * 13;

    const int a  = (int)st[0];
    const int pa0 = s_pp[a * 2], pa1 = s_pp[a * 2 + 1];
    const int mA  = s_pp[i * 2], mB  = s_pp[i * 2 + 1];

    // ---------- stage 0: pairs[i] = lane[mA] + lane[mB] ----------
    float pairs[16];
    #pragma unroll
    for (int c = 0; c < 16; c++) pairs[c] = 0.0f;

    #pragma unroll
    for (int t = 0; t < 2; t++) {
        const int m = (t == 0) ? mA : mB;
        const float dm = st[1 + m];
        float de[4];
        #pragma unroll
        for (int k = 0; k < 4; k++) de[k] = sigm(fmaf(dm, s_dw[k], s_db[k]));
        const int e = (m == pa0 || m == pa1) ? 1 : 0;
        #pragma unroll
        for (int c = 0; c < 16; c++) {
            float acc = s_base[e][c];
            #pragma unroll
            for (int k = 0; k < 4; k++) acc = fmaf(de[k], s_leD[k][c], acc);
            pairs[c] += fmaxf(acc, 0.0f);
        }
    }

    // ---------- stage 1: packed-by-c u/v matvec -> shared ----------
    const int slot = g * G_STRIDE + i * 20;
    {
        ull pp2[8];
        #pragma unroll
        for (int k = 0; k < 8; k++) pp2[k] = f2pack(pairs[2 * k], pairs[2 * k + 1]);

        float4* u4p = reinterpret_cast<float4*>(&s_u[slot]);
        float4* v4p = reinterpret_cast<float4*>(&s_v[slot]);
        #pragma unroll 1
        for (int ob = 0; ob < 5; ob++) {
            float ur[4], vr[4];
            #pragma unroll
            for (int oi = 0; oi < 4; oi++) {
                const int o = ob * 4 + oi;
                const ulonglong2* wa = reinterpret_cast<const ulonglong2*>(&s_lcA[o][0]);
                const ulonglong2* wb = reinterpret_cast<const ulonglong2*>(&s_lcB[o][0]);
                ull au = 0ULL, av = 0ULL;
                #pragma unroll
                for (int k = 0; k < 4; k++) {
                    ulonglong2 A = wa[k], Bv = wb[k];
                    au = f2fma(A.x,  pp2[2 * k + 0], au);
                    av = f2fma(Bv.x, pp2[2 * k + 0], av);
                    au = f2fma(A.y,  pp2[2 * k + 1], au);
                    av = f2fma(Bv.y, pp2[2 * k + 1], av);
                }
                ur[oi] = f2hadd(au) + s_lcb[o];
                vr[oi] = f2hadd(av);
            }
            u4p[ob] = make_float4(ur[0], ur[1], ur[2], ur[3]);
            v4p[ob] = make_float4(vr[0], vr[1], vr[2], vr[3]);
        }
    }
    __syncthreads();

    // ---------- stage 2: q chunked by 4 (weights amortized 4x); comb built scalar ----------
    const int gv = g * G_STRIDE;
    float acc = 0.0f;

    #pragma unroll 1
    for (int qc = 0; qc < 2; qc++) {
        const int qb = qc * 4;
        ull cb[4][10];
        {
            // u reloaded per chunk (transient 20 floats; frees persistent regs)
            float uu[20];
            const float4* u4 = reinterpret_cast<const float4*>(&s_u[slot]);
            #pragma unroll
            for (int k = 0; k < 5; k++) {
                float4 t = u4[k];
                uu[4*k+0] = t.x; uu[4*k+1] = t.y; uu[4*k+2] = t.z; uu[4*k+3] = t.w;
            }

            #pragma unroll
            for (int qq = 0; qq < 4; qq++) {
                const int q = qb + qq;
                const float4* vq = reinterpret_cast<const float4*>(&s_v[gv + q * 20]);
                const float4* rq = reinterpret_cast<const float4*>(&s_rel[(q * 8 + i) * 20]);
                #pragma unroll
                for (int k = 0; k < 5; k++) {
                    float4 vv = vq[k], rr = rq[k];
                    float x0 = fmaxf(uu[4*k+0] + vv.x, 0.0f) * rr.x;
                    float x1 = fmaxf(uu[4*k+1] + vv.y, 0.0f) * rr.y;
                    float x2 = fmaxf(uu[4*k+2] + vv.z, 0.0f) * rr.z;
                    float x3 = fmaxf(uu[4*k+3] + vv.w, 0.0f) * rr.w;
                    cb[qq][2*k+0] = f2pack(x0, x1);
                    cb[qq][2*k+1] = f2pack(x2, x3);
                }
            }
        }

        #pragma unroll 1
        for (int o = 0; o < 20; o++) {
            const ulonglong2* w2 = reinterpret_cast<const ulonglong2*>(&s_hw[o][0]);
            ull h0 = s_hb2[o], h1 = h0, h2 = h0, h3 = h0;   // 4 independent chains
            #pragma unroll
            for (int k = 0; k < 5; k++) {
                ulonglong2 w = w2[k];
                h0 = f2fma(w.x, cb[0][2*k+0], h0);
                h1 = f2fma(w.x, cb[1][2*k+0], h1);
                h2 = f2fma(w.x, cb[2][2*k+0], h2);
                h3 = f2fma(w.x, cb[3][2*k+0], h3);
                h0 = f2fma(w.y, cb[0][2*k+1], h0);
                h1 = f2fma(w.y, cb[1][2*k+1], h1);
                h2 = f2fma(w.y, cb[2][2*k+1], h2);
                h3 = f2fma(w.y, cb[3][2*k+1], h3);
            }
            const float bw = s_bmw[o];
            acc = fmaf(bw, fmaxf(f2hadd(h0), 0.0f), acc);
            acc = fmaf(bw, fmaxf(f2hadd(h1), 0.0f), acc);
            acc = fmaf(bw, fmaxf(f2hadd(h2), 0.0f), acc);
            acc = fmaf(bw, fmaxf(f2hadd(h3), 0.0f), acc);
        }
    }

    // subtract dummy-q contribution (comb=0 -> h=h_b), add 7x bm bias
    if (valid) out[b * 8 + i] = acc - s_corr + 7.0f * s_bmb;
}

extern "C" void kernel_launch(void* const* d_in, const int* in_sizes, int n_in,
                              void* d_out, int out_size)
{
    const float* states      = (const float*)d_in[0];
    const int*   comp_mask   = (const int*)  d_in[1];
    const int*   phase_pairs = (const int*)  d_in[2];
    const float* p_w  = (const float*)d_in[3];
    const float* d_w  = (const float*)d_in[4];
    const float* d_b  = (const float*)d_in[5];
    const float* le_w = (const float*)d_in[6];
    const float* le_b = (const float*)d_in[7];
    const float* lc_w = (const float*)d_in[8];
    const float* lc_b = (const float*)d_in[9];
    const float* rel_w = (const float*)d_in[10];
    const float* rc_w  = (const float*)d_in[11];
    const float* rc_b  = (const float*)d_in[12];
    const float* h_w   = (const float*)d_in[13];
    const float* h_b   = (const float*)d_in[14];
    const float* bm_w  = (const float*)d_in[15];
    const float* bm_b  = (const float*)d_in[16];

    const int B = in_sizes[0] / 13;           // states is [B, 1 + 12]
    const int blocks = (B + 15) / 16;         // 16 batch elems x 8 phases per 128-thread block

    frap_kernel<<<blocks, 128>>>(states, comp_mask, phase_pairs,
                                 p_w, d_w, d_b, le_w, le_b, lc_w, lc_b,
                                 rel_w, rc_w, rc_b, h_w, h_b, bm_w, bm_b,
                                 (float*)d_out, B);
}

// round 13
// speedup vs baseline: 1.1186x; 1.0676x over previous
#include <cuda_runtime.h>
#include <cstdint>

using ull = unsigned long long;

// ---------- packed f32x2 helpers (pack axis = channel c) ----------
__device__ __forceinline__ ull f2fma(ull a, ull b, ull c) {
    ull d; asm("fma.rn.f32x2 %0, %1, %2, %3;" : "=l"(d) : "l"(a), "l"(b), "l"(c)); return d;
}
__device__ __forceinline__ float f2hadd(ull p) {
    float a, b; asm("mov.b64 {%0, %1}, %2;" : "=f"(a), "=f"(b) : "l"(p));
    return a + b;
}
__device__ __forceinline__ ull f2pack(float a, float b) {
    ull r; asm("mov.b64 %0, {%1, %2};" : "=l"(r) : "f"(a), "f"(b)); return r;
}
__device__ __forceinline__ float sigm(float x) { return 1.0f / (1.0f + __expf(-x)); }

// u/v exchange layout (floats): addr = g*168 + phase*20 + c.
// 168 mod 32 = 8 -> 4 per-warp g-bases hit bank quads 0/8/16/24.
#define G_STRIDE 168

__global__ __launch_bounds__(128, 4)
void frap_kernel(const float* __restrict__ states,
                 const int*   __restrict__ comp_mask,
                 const int*   __restrict__ phase_pairs,
                 const float* __restrict__ p_w,
                 const float* __restrict__ d_w,  const float* __restrict__ d_b,
                 const float* __restrict__ le_w, const float* __restrict__ le_b,
                 const float* __restrict__ lc_w, const float* __restrict__ lc_b,
                 const float* __restrict__ rel_w,
                 const float* __restrict__ rc_w, const float* __restrict__ rc_b,
                 const float* __restrict__ h_w,  const float* __restrict__ h_b,
                 const float* __restrict__ bm_w, const float* __restrict__ bm_b,
                 float* __restrict__ out, int B)
{
    __shared__ __align__(16) float s_lcA[20][16];     // lc_w[:, 0:16]
    __shared__ __align__(16) float s_lcB[20][16];     // lc_w[:, 16:32]
    __shared__ __align__(16) float s_hw[20][20];      // natural c-pairs for f32x2
    __shared__ __align__(16) float s_rel[56 * 20];    // [i][q] compact (7 real q per i)
    __shared__ float s_leD[4][16];
    __shared__ float s_lcb[20], s_bmw[20], s_dw[4], s_db[4];
    __shared__ ull   s_hb2[20];                       // packed (h_b[o], 0)
    __shared__ float s_base[2][16];
    __shared__ int   s_pp[16];
    __shared__ float s_bmb;
    __shared__ __align__(16) float s_u[16 * G_STRIDE];
    __shared__ __align__(16) float s_v[16 * G_STRIDE];

    const int tid = threadIdx.x;

    // ---------------- block-local precompute ----------------
    for (int idx = tid; idx < 320; idx += 128) {
        int o = idx >> 4, c = idx & 15;
        s_lcA[o][c] = lc_w[o * 32 + c];
        s_lcB[o][c] = lc_w[o * 32 + 16 + c];
    }
    for (int idx = tid; idx < 400; idx += 128) {
        int o = idx / 20, c = idx % 20;
        s_hw[o][c] = h_w[o * 20 + c];
    }
    // s_rel[i*7+q][o] = relu(relu(rel_w[comp_mask[i][q]]) @ rc_w^T + rc_b)
    for (int idx = tid; idx < 1120; idx += 128) {
        int pq = idx / 20, o = idx % 20;
        int e = comp_mask[pq];
        float acc = rc_b[o];
        #pragma unroll
        for (int c4 = 0; c4 < 4; c4++)
            acc += fmaxf(rel_w[e * 4 + c4], 0.0f) * rc_w[o * 4 + c4];
        s_rel[pq * 20 + o] = fmaxf(acc, 0.0f);
    }
    for (int idx = tid; idx < 64; idx += 128) {
        int k = idx >> 4, c = idx & 15;
        s_leD[k][c] = le_w[(4 + k) * 16 + c];
    }
    if (tid < 32) {
        int e = tid >> 4, c = tid & 15;
        float a = le_b[c];
        #pragma unroll
        for (int k = 0; k < 4; k++) a += sigm(p_w[e * 4 + k]) * le_w[k * 16 + c];
        s_base[e][c] = a;
    }
    if (tid < 20) {
        s_lcb[tid] = lc_b[tid];
        s_bmw[tid] = bm_w[tid];
        s_hb2[tid] = f2pack(h_b[tid], 0.0f);
    }
    if (tid < 4) { s_dw[tid] = d_w[tid]; s_db[tid] = d_b[tid]; }
    if (tid < 16) s_pp[tid] = phase_pairs[tid];
    if (tid == 0) s_bmb = bm_b[0];
    __syncthreads();

    // ---------------- per-thread: (batch elem b) x (output phase i) ----------------
    const int g = tid >> 3;
    const int i = tid & 7;
    const int b = blockIdx.x * 16 + g;
    const bool valid = (b < B);
    const float* st = states + (valid ? b : 0) * 13;

    const int a  = (int)st[0];
    const int pa0 = s_pp[a * 2], pa1 = s_pp[a * 2 + 1];
    const int mA  = s_pp[i * 2], mB  = s_pp[i * 2 + 1];

    // ---------- stage 0: pairs[i] = lane[mA] + lane[mB] ----------
    float pairs[16];
    #pragma unroll
    for (int c = 0; c < 16; c++) pairs[c] = 0.0f;

    #pragma unroll
    for (int t = 0; t < 2; t++) {
        const int m = (t == 0) ? mA : mB;
        const float dm = st[1 + m];
        float de[4];
        #pragma unroll
        for (int k = 0; k < 4; k++) de[k] = sigm(fmaf(dm, s_dw[k], s_db[k]));
        const int e = (m == pa0 || m == pa1) ? 1 : 0;
        #pragma unroll
        for (int c = 0; c < 16; c++) {
            float acc = s_base[e][c];
            #pragma unroll
            for (int k = 0; k < 4; k++) acc = fmaf(de[k], s_leD[k][c], acc);
            pairs[c] += fmaxf(acc, 0.0f);
        }
    }

    // ---------- stage 1: packed-by-c u/v matvec -> shared ----------
    const int slot = g * G_STRIDE + i * 20;
    {
        ull pp2[8];
        #pragma unroll
        for (int k = 0; k < 8; k++) pp2[k] = f2pack(pairs[2 * k], pairs[2 * k + 1]);

        float4* u4p = reinterpret_cast<float4*>(&s_u[slot]);
        float4* v4p = reinterpret_cast<float4*>(&s_v[slot]);
        #pragma unroll 1
        for (int ob = 0; ob < 5; ob++) {
            float ur[4], vr[4];
            #pragma unroll
            for (int oi = 0; oi < 4; oi++) {
                const int o = ob * 4 + oi;
                const ulonglong2* wa = reinterpret_cast<const ulonglong2*>(&s_lcA[o][0]);
                const ulonglong2* wb = reinterpret_cast<const ulonglong2*>(&s_lcB[o][0]);
                ull au = 0ULL, av = 0ULL;
                #pragma unroll
                for (int k = 0; k < 4; k++) {
                    ulonglong2 A = wa[k], Bv = wb[k];
                    au = f2fma(A.x,  pp2[2 * k + 0], au);
                    av = f2fma(Bv.x, pp2[2 * k + 0], av);
                    au = f2fma(A.y,  pp2[2 * k + 1], au);
                    av = f2fma(Bv.y, pp2[2 * k + 1], av);
                }
                ur[oi] = f2hadd(au) + s_lcb[o];
                vr[oi] = f2hadd(av);
            }
            u4p[ob] = make_float4(ur[0], ur[1], ur[2], ur[3]);
            v4p[ob] = make_float4(vr[0], vr[1], vr[2], vr[3]);
        }
    }
    __syncthreads();

    // ---------- stage 2: 7 REAL q's, chunked 4 + 3 (no dummy) ----------
    const int gv = g * G_STRIDE;
    float acc = 0.0f;

    // ----- chunk A: q = 0..3 -----
    {
        float uu[20];
        const float4* u4 = reinterpret_cast<const float4*>(&s_u[slot]);
        #pragma unroll
        for (int k = 0; k < 5; k++) {
            float4 t = u4[k];
            uu[4*k+0] = t.x; uu[4*k+1] = t.y; uu[4*k+2] = t.z; uu[4*k+3] = t.w;
        }

        ull cb[4][10];
        #pragma unroll
        for (int qq = 0; qq < 4; qq++) {
            const int j = qq + (qq >= i ? 1 : 0);
            const float4* vq = reinterpret_cast<const float4*>(&s_v[gv + j * 20]);
            const float4* rq = reinterpret_cast<const float4*>(&s_rel[(i * 7 + qq) * 20]);
            #pragma unroll
            for (int k = 0; k < 5; k++) {
                float4 vv = vq[k], rr = rq[k];
                float x0 = fmaxf(uu[4*k+0] + vv.x, 0.0f) * rr.x;
                float x1 = fmaxf(uu[4*k+1] + vv.y, 0.0f) * rr.y;
                float x2 = fmaxf(uu[4*k+2] + vv.z, 0.0f) * rr.z;
                float x3 = fmaxf(uu[4*k+3] + vv.w, 0.0f) * rr.w;
                cb[qq][2*k+0] = f2pack(x0, x1);
                cb[qq][2*k+1] = f2pack(x2, x3);
            }
        }

        #pragma unroll 1
        for (int o = 0; o < 20; o++) {
            const ulonglong2* w2 = reinterpret_cast<const ulonglong2*>(&s_hw[o][0]);
            ull h0 = s_hb2[o], h1 = h0, h2 = h0, h3 = h0;
            #pragma unroll
            for (int k = 0; k < 5; k++) {
                ulonglong2 w = w2[k];
                h0 = f2fma(w.x, cb[0][2*k+0], h0);
                h1 = f2fma(w.x, cb[1][2*k+0], h1);
                h2 = f2fma(w.x, cb[2][2*k+0], h2);
                h3 = f2fma(w.x, cb[3][2*k+0], h3);
                h0 = f2fma(w.y, cb[0][2*k+1], h0);
                h1 = f2fma(w.y, cb[1][2*k+1], h1);
                h2 = f2fma(w.y, cb[2][2*k+1], h2);
                h3 = f2fma(w.y, cb[3][2*k+1], h3);
            }
            const float bw = s_bmw[o];
            acc = fmaf(bw, fmaxf(f2hadd(h0), 0.0f), acc);
            acc = fmaf(bw, fmaxf(f2hadd(h1), 0.0f), acc);
            acc = fmaf(bw, fmaxf(f2hadd(h2), 0.0f), acc);
            acc = fmaf(bw, fmaxf(f2hadd(h3), 0.0f), acc);
        }
    }

    // ----- chunk B: q = 4..6 -----
    {
        float uu[20];
        const float4* u4 = reinterpret_cast<const float4*>(&s_u[slot]);
        #pragma unroll
        for (int k = 0; k < 5; k++) {
            float4 t = u4[k];
            uu[4*k+0] = t.x; uu[4*k+1] = t.y; uu[4*k+2] = t.z; uu[4*k+3] = t.w;
        }

        ull cb[3][10];
        #pragma unroll
        for (int qq = 0; qq < 3; qq++) {
            const int q = 4 + qq;
            const int j = q + (q >= i ? 1 : 0);
            const float4* vq = reinterpret_cast<const float4*>(&s_v[gv + j * 20]);
            const float4* rq = reinterpret_cast<const float4*>(&s_rel[(i * 7 + q) * 20]);
            #pragma unroll
            for (int k = 0; k < 5; k++) {
                float4 vv = vq[k], rr = rq[k];
                float x0 = fmaxf(uu[4*k+0] + vv.x, 0.0f) * rr.x;
                float x1 = fmaxf(uu[4*k+1] + vv.y, 0.0f) * rr.y;
                float x2 = fmaxf(uu[4*k+2] + vv.z, 0.0f) * rr.z;
                float x3 = fmaxf(uu[4*k+3] + vv.w, 0.0f) * rr.w;
                cb[qq][2*k+0] = f2pack(x0, x1);
                cb[qq][2*k+1] = f2pack(x2, x3);
            }
        }

        #pragma unroll 1
        for (int o = 0; o < 20; o++) {
            const ulonglong2* w2 = reinterpret_cast<const ulonglong2*>(&s_hw[o][0]);
            ull h0 = s_hb2[o], h1 = h0, h2 = h0;
            #pragma unroll
            for (int k = 0; k < 5; k++) {
                ulonglong2 w = w2[k];
                h0 = f2fma(w.x, cb[0][2*k+0], h0);
                h1 = f2fma(w.x, cb[1][2*k+0], h1);
                h2 = f2fma(w.x, cb[2][2*k+0], h2);
                h0 = f2fma(w.y, cb[0][2*k+1], h0);
                h1 = f2fma(w.y, cb[1][2*k+1], h1);
                h2 = f2fma(w.y, cb[2][2*k+1], h2);
            }
            const float bw = s_bmw[o];
            acc = fmaf(bw, fmaxf(f2hadd(h0), 0.0f), acc);
            acc = fmaf(bw, fmaxf(f2hadd(h1), 0.0f), acc);
            acc = fmaf(bw, fmaxf(f2hadd(h2), 0.0f), acc);
        }
    }

    if (valid) out[b * 8 + i] = acc + 7.0f * s_bmb;
}

extern "C" void kernel_launch(void* const* d_in, const int* in_sizes, int n_in,
                              void* d_out, int out_size)
{
    const float* states      = (const float*)d_in[0];
    const int*   comp_mask   = (const int*)  d_in[1];
    const int*   phase_pairs = (const int*)  d_in[2];
    const float* p_w  = (const float*)d_in[3];
    const float* d_w  = (const float*)d_in[4];
    const float* d_b  = (const float*)d_in[5];
    const float* le_w = (const float*)d_in[6];
    const float* le_b = (const float*)d_in[7];
    const float* lc_w = (const float*)d_in[8];
    const float* lc_b = (const float*)d_in[9];
    const float* rel_w = (const float*)d_in[10];
    const float* rc_w  = (const float*)d_in[11];
    const float* rc_b  = (const float*)d_in[12];
    const float* h_w   = (const float*)d_in[13];
    const float* h_b   = (const float*)d_in[14];
    const float* bm_w  = (const float*)d_in[15];
    const float* bm_b  = (const float*)d_in[16];

    const int B = in_sizes[0] / 13;           // states is [B, 1 + 12]
    const int blocks = (B + 15) / 16;         // 16 batch elems x 8 phases per 128-thread block

    frap_kernel<<<blocks, 128>>>(states, comp_mask, phase_pairs,
                                 p_w, d_w, d_b, le_w, le_b, lc_w, lc_b,
                                 rel_w, rc_w, rc_b, h_w, h_b, bm_w, bm_b,
                                 (float*)d_out, B);
}

// round 14
// speedup vs baseline: 1.1741x; 1.0497x over previous
#include <cuda_runtime.h>
#include <cstdint>

using ull = unsigned long long;

// ---------- packed f32x2 helpers (pack axis = channel c) ----------
__device__ __forceinline__ ull f2fma(ull a, ull b, ull c) {
    ull d; asm("fma.rn.f32x2 %0, %1, %2, %3;" : "=l"(d) : "l"(a), "l"(b), "l"(c)); return d;
}
__device__ __forceinline__ float f2hadd(ull p) {
    float a, b; asm("mov.b64 {%0, %1}, %2;" : "=f"(a), "=f"(b) : "l"(p));
    return a + b;
}
__device__ __forceinline__ ull f2pack(float a, float b) {
    ull r; asm("mov.b64 %0, {%1, %2};" : "=l"(r) : "f"(a), "f"(b)); return r;
}
__device__ __forceinline__ float sigm(float x) { return 1.0f / (1.0f + __expf(-x)); }

// u/v exchange layout (floats): addr = g*168 + phase*20 + c.
// 168 mod 32 = 8 -> 4 per-warp g-bases hit bank quads 0/8/16/24.
#define G_STRIDE 168
#define PERSIST_BLOCKS 592   // 148 SMs x 4 blocks/SM: all blocks resident, no waves

__global__ __launch_bounds__(128, 4)
void frap_kernel(const float* __restrict__ states,
                 const int*   __restrict__ comp_mask,
                 const int*   __restrict__ phase_pairs,
                 const float* __restrict__ p_w,
                 const float* __restrict__ d_w,  const float* __restrict__ d_b,
                 const float* __restrict__ le_w, const float* __restrict__ le_b,
                 const float* __restrict__ lc_w, const float* __restrict__ lc_b,
                 const float* __restrict__ rel_w,
                 const float* __restrict__ rc_w, const float* __restrict__ rc_b,
                 const float* __restrict__ h_w,  const float* __restrict__ h_b,
                 const float* __restrict__ bm_w, const float* __restrict__ bm_b,
                 float* __restrict__ out, int B, int numTiles)
{
    __shared__ __align__(16) float s_lcA[20][16];     // lc_w[:, 0:16]
    __shared__ __align__(16) float s_lcB[20][16];     // lc_w[:, 16:32]
    __shared__ __align__(16) float s_hw[20][20];      // natural c-pairs for f32x2
    __shared__ __align__(16) float s_rel[56 * 20];    // [i][q] compact
    __shared__ float s_leD[4][16];
    __shared__ float s_lcb[20], s_bmw[20], s_dw[4], s_db[4];
    __shared__ ull   s_hb2[20];                       // packed (h_b[o], 0)
    __shared__ float s_base[2][16];
    __shared__ int   s_pp[16];
    __shared__ float s_bmb;
    __shared__ __align__(16) float s_u[16 * G_STRIDE];
    __shared__ __align__(16) float s_v[16 * G_STRIDE];

    const int tid = threadIdx.x;

    // ---------------- precompute ONCE per persistent block ----------------
    for (int idx = tid; idx < 320; idx += 128) {
        int o = idx >> 4, c = idx & 15;
        s_lcA[o][c] = lc_w[o * 32 + c];
        s_lcB[o][c] = lc_w[o * 32 + 16 + c];
    }
    for (int idx = tid; idx < 400; idx += 128) {
        int o = idx / 20, c = idx % 20;
        s_hw[o][c] = h_w[o * 20 + c];
    }
    for (int idx = tid; idx < 1120; idx += 128) {
        int pq = idx / 20, o = idx % 20;
        int e = comp_mask[pq];
        float acc = rc_b[o];
        #pragma unroll
        for (int c4 = 0; c4 < 4; c4++)
            acc += fmaxf(rel_w[e * 4 + c4], 0.0f) * rc_w[o * 4 + c4];
        s_rel[pq * 20 + o] = fmaxf(acc, 0.0f);
    }
    for (int idx = tid; idx < 64; idx += 128) {
        int k = idx >> 4, c = idx & 15;
        s_leD[k][c] = le_w[(4 + k) * 16 + c];
    }
    if (tid < 32) {
        int e = tid >> 4, c = tid & 15;
        float a = le_b[c];
        #pragma unroll
        for (int k = 0; k < 4; k++) a += sigm(p_w[e * 4 + k]) * le_w[k * 16 + c];
        s_base[e][c] = a;
    }
    if (tid < 20) {
        s_lcb[tid] = lc_b[tid];
        s_bmw[tid] = bm_w[tid];
        s_hb2[tid] = f2pack(h_b[tid], 0.0f);
    }
    if (tid < 4) { s_dw[tid] = d_w[tid]; s_db[tid] = d_b[tid]; }
    if (tid < 16) s_pp[tid] = phase_pairs[tid];
    if (tid == 0) s_bmb = bm_b[0];
    __syncthreads();

    const int g = tid >> 3;
    const int i = tid & 7;
    const int mA = s_pp[i * 2], mB = s_pp[i * 2 + 1];
    const int slot = g * G_STRIDE + i * 20;
    const int gv = g * G_STRIDE;
    const float bias7 = 7.0f * s_bmb;

    // ---------------- persistent tile loop ----------------
    for (int tile = blockIdx.x; tile < numTiles; tile += gridDim.x) {
        const int b = tile * 16 + g;
        const bool valid = (b < B);
        const float* st = states + (valid ? b : 0) * 13;

        const int a  = (int)st[0];
        const int pa0 = s_pp[a * 2], pa1 = s_pp[a * 2 + 1];

        // ---------- stage 0: pairs[i] = lane[mA] + lane[mB] ----------
        float pairs[16];
        #pragma unroll
        for (int c = 0; c < 16; c++) pairs[c] = 0.0f;

        #pragma unroll
        for (int t = 0; t < 2; t++) {
            const int m = (t == 0) ? mA : mB;
            const float dm = st[1 + m];
            float de[4];
            #pragma unroll
            for (int k = 0; k < 4; k++) de[k] = sigm(fmaf(dm, s_dw[k], s_db[k]));
            const int e = (m == pa0 || m == pa1) ? 1 : 0;
            #pragma unroll
            for (int c = 0; c < 16; c++) {
                float acc = s_base[e][c];
                #pragma unroll
                for (int k = 0; k < 4; k++) acc = fmaf(de[k], s_leD[k][c], acc);
                pairs[c] += fmaxf(acc, 0.0f);
            }
        }

        // ---------- stage 1: packed-by-c u/v matvec -> shared ----------
        {
            ull pp2[8];
            #pragma unroll
            for (int k = 0; k < 8; k++) pp2[k] = f2pack(pairs[2 * k], pairs[2 * k + 1]);

            float4* u4p = reinterpret_cast<float4*>(&s_u[slot]);
            float4* v4p = reinterpret_cast<float4*>(&s_v[slot]);
            #pragma unroll 1
            for (int ob = 0; ob < 5; ob++) {
                float ur[4], vr[4];
                #pragma unroll
                for (int oi = 0; oi < 4; oi++) {
                    const int o = ob * 4 + oi;
                    const ulonglong2* wa = reinterpret_cast<const ulonglong2*>(&s_lcA[o][0]);
                    const ulonglong2* wb = reinterpret_cast<const ulonglong2*>(&s_lcB[o][0]);
                    ull au = 0ULL, av = 0ULL;
                    #pragma unroll
                    for (int k = 0; k < 4; k++) {
                        ulonglong2 A = wa[k], Bv = wb[k];
                        au = f2fma(A.x,  pp2[2 * k + 0], au);
                        av = f2fma(Bv.x, pp2[2 * k + 0], av);
                        au = f2fma(A.y,  pp2[2 * k + 1], au);
                        av = f2fma(Bv.y, pp2[2 * k + 1], av);
                    }
                    ur[oi] = f2hadd(au) + s_lcb[o];
                    vr[oi] = f2hadd(av);
                }
                u4p[ob] = make_float4(ur[0], ur[1], ur[2], ur[3]);
                v4p[ob] = make_float4(vr[0], vr[1], vr[2], vr[3]);
            }
        }
        __syncthreads();

        // ---------- stage 2: 7 real q's, chunked 4 + 3 ----------
        float acc = 0.0f;

        // ----- chunk A: q = 0..3 -----
        {
            float uu[20];
            const float4* u4 = reinterpret_cast<const float4*>(&s_u[slot]);
            #pragma unroll
            for (int k = 0; k < 5; k++) {
                float4 t = u4[k];
                uu[4*k+0] = t.x; uu[4*k+1] = t.y; uu[4*k+2] = t.z; uu[4*k+3] = t.w;
            }

            ull cb[4][10];
            #pragma unroll
            for (int qq = 0; qq < 4; qq++) {
                const int j = qq + (qq >= i ? 1 : 0);
                const float4* vq = reinterpret_cast<const float4*>(&s_v[gv + j * 20]);
                const float4* rq = reinterpret_cast<const float4*>(&s_rel[(i * 7 + qq) * 20]);
                #pragma unroll
                for (int k = 0; k < 5; k++) {
                    float4 vv = vq[k], rr = rq[k];
                    float x0 = fmaxf(uu[4*k+0] + vv.x, 0.0f) * rr.x;
                    float x1 = fmaxf(uu[4*k+1] + vv.y, 0.0f) * rr.y;
                    float x2 = fmaxf(uu[4*k+2] + vv.z, 0.0f) * rr.z;
                    float x3 = fmaxf(uu[4*k+3] + vv.w, 0.0f) * rr.w;
                    cb[qq][2*k+0] = f2pack(x0, x1);
                    cb[qq][2*k+1] = f2pack(x2, x3);
                }
            }

            #pragma unroll 1
            for (int o = 0; o < 20; o++) {
                const ulonglong2* w2 = reinterpret_cast<const ulonglong2*>(&s_hw[o][0]);
                ull h0 = s_hb2[o], h1 = h0, h2 = h0, h3 = h0;
                #pragma unroll
                for (int k = 0; k < 5; k++) {
                    ulonglong2 w = w2[k];
                    h0 = f2fma(w.x, cb[0][2*k+0], h0);
                    h1 = f2fma(w.x, cb[1][2*k+0], h1);
                    h2 = f2fma(w.x, cb[2][2*k+0], h2);
                    h3 = f2fma(w.x, cb[3][2*k+0], h3);
                    h0 = f2fma(w.y, cb[0][2*k+1], h0);
                    h1 = f2fma(w.y, cb[1][2*k+1], h1);
                    h2 = f2fma(w.y, cb[2][2*k+1], h2);
                    h3 = f2fma(w.y, cb[3][2*k+1], h3);
                }
                const float bw = s_bmw[o];
                acc = fmaf(bw, fmaxf(f2hadd(h0), 0.0f), acc);
                acc = fmaf(bw, fmaxf(f2hadd(h1), 0.0f), acc);
                acc = fmaf(bw, fmaxf(f2hadd(h2), 0.0f), acc);
                acc = fmaf(bw, fmaxf(f2hadd(h3), 0.0f), acc);
            }
        }

        // ----- chunk B: q = 4..6 -----
        {
            float uu[20];
            const float4* u4 = reinterpret_cast<const float4*>(&s_u[slot]);
            #pragma unroll
            for (int k = 0; k < 5; k++) {
                float4 t = u4[k];
                uu[4*k+0] = t.x; uu[4*k+1] = t.y; uu[4*k+2] = t.z; uu[4*k+3] = t.w;
            }

            ull cb[3][10];
            #pragma unroll
            for (int qq = 0; qq < 3; qq++) {
                const int q = 4 + qq;
                const int j = q + (q >= i ? 1 : 0);
                const float4* vq = reinterpret_cast<const float4*>(&s_v[gv + j * 20]);
                const float4* rq = reinterpret_cast<const float4*>(&s_rel[(i * 7 + q) * 20]);
                #pragma unroll
                for (int k = 0; k < 5; k++) {
                    float4 vv = vq[k], rr = rq[k];
                    float x0 = fmaxf(uu[4*k+0] + vv.x, 0.0f) * rr.x;
                    float x1 = fmaxf(uu[4*k+1] + vv.y, 0.0f) * rr.y;
                    float x2 = fmaxf(uu[4*k+2] + vv.z, 0.0f) * rr.z;
                    float x3 = fmaxf(uu[4*k+3] + vv.w, 0.0f) * rr.w;
                    cb[qq][2*k+0] = f2pack(x0, x1);
                    cb[qq][2*k+1] = f2pack(x2, x3);
                }
            }

            #pragma unroll 1
            for (int o = 0; o < 20; o++) {
                const ulonglong2* w2 = reinterpret_cast<const ulonglong2*>(&s_hw[o][0]);
                ull h0 = s_hb2[o], h1 = h0, h2 = h0;
                #pragma unroll
                for (int k = 0; k < 5; k++) {
                    ulonglong2 w = w2[k];
                    h0 = f2fma(w.x, cb[0][2*k+0], h0);
                    h1 = f2fma(w.x, cb[1][2*k+0], h1);
                    h2 = f2fma(w.x, cb[2][2*k+0], h2);
                    h0 = f2fma(w.y, cb[0][2*k+1], h0);
                    h1 = f2fma(w.y, cb[1][2*k+1], h1);
                    h2 = f2fma(w.y, cb[2][2*k+1], h2);
                }
                const float bw = s_bmw[o];
                acc = fmaf(bw, fmaxf(f2hadd(h0), 0.0f), acc);
                acc = fmaf(bw, fmaxf(f2hadd(h1), 0.0f), acc);
                acc = fmaf(bw, fmaxf(f2hadd(h2), 0.0f), acc);
            }
        }

        if (valid) out[b * 8 + i] = acc + bias7;

        __syncthreads();   // protect s_u/s_v before next tile's stage-1 writes
    }
}

extern "C" void kernel_launch(void* const* d_in, const int* in_sizes, int n_in,
                              void* d_out, int out_size)
{
    const float* states      = (const float*)d_in[0];
    const int*   comp_mask   = (const int*)  d_in[1];
    const int*   phase_pairs = (const int*)  d_in[2];
    const float* p_w  = (const float*)d_in[3];
    const float* d_w  = (const float*)d_in[4];
    const float* d_b  = (const float*)d_in[5];
    const float* le_w = (const float*)d_in[6];
    const float* le_b = (const float*)d_in[7];
    const float* lc_w = (const float*)d_in[8];
    const float* lc_b = (const float*)d_in[9];
    const float* rel_w = (const float*)d_in[10];
    const float* rc_w  = (const float*)d_in[11];
    const float* rc_b  = (const float*)d_in[12];
    const float* h_w   = (const float*)d_in[13];
    const float* h_b   = (const float*)d_in[14];
    const float* bm_w  = (const float*)d_in[15];
    const float* bm_b  = (const float*)d_in[16];

    const int B = in_sizes[0] / 13;             // states is [B, 1 + 12]
    const int numTiles = (B + 15) / 16;
    const int blocks = numTiles < PERSIST_BLOCKS ? numTiles : PERSIST_BLOCKS;

    frap_kernel<<<blocks, 128>>>(states, comp_mask, phase_pairs,
                                 p_w, d_w, d_b, le_w, le_b, lc_w, lc_b,
                                 rel_w, rc_w, rc_b, h_w, h_b, bm_w, bm_b,
                                 (float*)d_out, B, numTiles);
}

// round 15
// speedup vs baseline: 1.1862x; 1.0102x over previous
#include <cuda_runtime.h>
#include <cstdint>

using ull = unsigned long long;

// ---------- packed f32x2 helpers (pack axis = channel c) ----------
__device__ __forceinline__ ull f2fma(ull a, ull b, ull c) {
    ull d; asm("fma.rn.f32x2 %0, %1, %2, %3;" : "=l"(d) : "l"(a), "l"(b), "l"(c)); return d;
}
__device__ __forceinline__ float f2hadd(ull p) {
    float a, b; asm("mov.b64 {%0, %1}, %2;" : "=f"(a), "=f"(b) : "l"(p));
    return a + b;
}
__device__ __forceinline__ ull f2pack(float a, float b) {
    ull r; asm("mov.b64 %0, {%1, %2};" : "=l"(r) : "f"(a), "f"(b)); return r;
}
__device__ __forceinline__ float sigm(float x) { return 1.0f / (1.0f + __expf(-x)); }

// u/v exchange layout (floats): addr = g*168 + phase*20 + c.
// 168 mod 32 = 8 -> 4 per-warp g-bases hit bank quads 0/8/16/24.
// KEY: the v-exchange is INTRA-WARP (each warp owns 4 whole g-groups) ->
// stage boundaries need only __syncwarp(), never __syncthreads().
#define G_STRIDE 168
#define PERSIST_BLOCKS 592   // 148 SMs x 4 blocks/SM: all blocks resident, no waves

__global__ __launch_bounds__(128, 4)
void frap_kernel(const float* __restrict__ states,
                 const int*   __restrict__ comp_mask,
                 const int*   __restrict__ phase_pairs,
                 const float* __restrict__ p_w,
                 const float* __restrict__ d_w,  const float* __restrict__ d_b,
                 const float* __restrict__ le_w, const float* __restrict__ le_b,
                 const float* __restrict__ lc_w, const float* __restrict__ lc_b,
                 const float* __restrict__ rel_w,
                 const float* __restrict__ rc_w, const float* __restrict__ rc_b,
                 const float* __restrict__ h_w,  const float* __restrict__ h_b,
                 const float* __restrict__ bm_w, const float* __restrict__ bm_b,
                 float* __restrict__ out, int B, int numTiles)
{
    __shared__ __align__(16) float s_lcA[20][16];     // lc_w[:, 0:16]
    __shared__ __align__(16) float s_lcB[20][16];     // lc_w[:, 16:32]
    __shared__ __align__(16) float s_hw[20][20];      // natural c-pairs for f32x2
    __shared__ __align__(16) float s_rel[56 * 20];    // [i][q] compact
    __shared__ float s_leD[4][16];
    __shared__ float s_lcb[20], s_bmw[20], s_dw[4], s_db[4];
    __shared__ ull   s_hb2[20];                       // packed (h_b[o], 0)
    __shared__ float s_base[2][16];
    __shared__ int   s_pp[16];
    __shared__ float s_bmb;
    __shared__ __align__(16) float s_u[16 * G_STRIDE];
    __shared__ __align__(16) float s_v[16 * G_STRIDE];

    const int tid = threadIdx.x;

    // ---------------- precompute ONCE per persistent block ----------------
    for (int idx = tid; idx < 320; idx += 128) {
        int o = idx >> 4, c = idx & 15;
        s_lcA[o][c] = lc_w[o * 32 + c];
        s_lcB[o][c] = lc_w[o * 32 + 16 + c];
    }
    for (int idx = tid; idx < 400; idx += 128) {
        int o = idx / 20, c = idx % 20;
        s_hw[o][c] = h_w[o * 20 + c];
    }
    for (int idx = tid; idx < 1120; idx += 128) {
        int pq = idx / 20, o = idx % 20;
        int e = comp_mask[pq];
        float acc = rc_b[o];
        #pragma unroll
        for (int c4 = 0; c4 < 4; c4++)
            acc += fmaxf(rel_w[e * 4 + c4], 0.0f) * rc_w[o * 4 + c4];
        s_rel[pq * 20 + o] = fmaxf(acc, 0.0f);
    }
    for (int idx = tid; idx < 64; idx += 128) {
        int k = idx >> 4, c = idx & 15;
        s_leD[k][c] = le_w[(4 + k) * 16 + c];
    }
    if (tid < 32) {
        int e = tid >> 4, c = tid & 15;
        float a = le_b[c];
        #pragma unroll
        for (int k = 0; k < 4; k++) a += sigm(p_w[e * 4 + k]) * le_w[k * 16 + c];
        s_base[e][c] = a;
    }
    if (tid < 20) {
        s_lcb[tid] = lc_b[tid];
        s_bmw[tid] = bm_w[tid];
        s_hb2[tid] = f2pack(h_b[tid], 0.0f);
    }
    if (tid < 4) { s_dw[tid] = d_w[tid]; s_db[tid] = d_b[tid]; }
    if (tid < 16) s_pp[tid] = phase_pairs[tid];
    if (tid == 0) s_bmb = bm_b[0];
    __syncthreads();   // one block-wide barrier total (weights are read-only after)

    const int g = tid >> 3;
    const int i = tid & 7;
    const int mA = s_pp[i * 2], mB = s_pp[i * 2 + 1];
    const int slot = g * G_STRIDE + i * 20;
    const int gv = g * G_STRIDE;
    const float bias7 = 7.0f * s_bmb;

    // ---------------- persistent tile loop (warps fully decoupled) ----------------
    for (int tile = blockIdx.x; tile < numTiles; tile += gridDim.x) {
        const int b = tile * 16 + g;
        const bool valid = (b < B);
        const float* st = states + (valid ? b : 0) * 13;

        const int a  = (int)st[0];
        const int pa0 = s_pp[a * 2], pa1 = s_pp[a * 2 + 1];

        // ---------- stage 0: pairs[i] = lane[mA] + lane[mB] ----------
        float pairs[16];
        #pragma unroll
        for (int c = 0; c < 16; c++) pairs[c] = 0.0f;

        #pragma unroll
        for (int t = 0; t < 2; t++) {
            const int m = (t == 0) ? mA : mB;
            const float dm = st[1 + m];
            float de[4];
            #pragma unroll
            for (int k = 0; k < 4; k++) de[k] = sigm(fmaf(dm, s_dw[k], s_db[k]));
            const int e = (m == pa0 || m == pa1) ? 1 : 0;
            #pragma unroll
            for (int c = 0; c < 16; c++) {
                float acc = s_base[e][c];
                #pragma unroll
                for (int k = 0; k < 4; k++) acc = fmaf(de[k], s_leD[k][c], acc);
                pairs[c] += fmaxf(acc, 0.0f);
            }
        }

        // ---------- stage 1: packed-by-c u/v matvec -> shared ----------
        {
            ull pp2[8];
            #pragma unroll
            for (int k = 0; k < 8; k++) pp2[k] = f2pack(pairs[2 * k], pairs[2 * k + 1]);

            float4* u4p = reinterpret_cast<float4*>(&s_u[slot]);
            float4* v4p = reinterpret_cast<float4*>(&s_v[slot]);
            #pragma unroll 1
            for (int ob = 0; ob < 5; ob++) {
                float ur[4], vr[4];
                #pragma unroll
                for (int oi = 0; oi < 4; oi++) {
                    const int o = ob * 4 + oi;
                    const ulonglong2* wa = reinterpret_cast<const ulonglong2*>(&s_lcA[o][0]);
                    const ulonglong2* wb = reinterpret_cast<const ulonglong2*>(&s_lcB[o][0]);
                    ull au = 0ULL, av = 0ULL;
                    #pragma unroll
                    for (int k = 0; k < 4; k++) {
                        ulonglong2 A = wa[k], Bv = wb[k];
                        au = f2fma(A.x,  pp2[2 * k + 0], au);
                        av = f2fma(Bv.x, pp2[2 * k + 0], av);
                        au = f2fma(A.y,  pp2[2 * k + 1], au);
                        av = f2fma(Bv.y, pp2[2 * k + 1], av);
                    }
                    ur[oi] = f2hadd(au) + s_lcb[o];
                    vr[oi] = f2hadd(av);
                }
                u4p[ob] = make_float4(ur[0], ur[1], ur[2], ur[3]);
                v4p[ob] = make_float4(vr[0], vr[1], vr[2], vr[3]);
            }
        }
        __syncwarp();   // v-exchange is intra-warp: warp-local fence suffices

        // ---------- stage 2: 7 real q's, chunked 4 + 3 ----------
        float acc = 0.0f;

        // ----- chunk A: q = 0..3 -----
        {
            float uu[20];
            const float4* u4 = reinterpret_cast<const float4*>(&s_u[slot]);
            #pragma unroll
            for (int k = 0; k < 5; k++) {
                float4 t = u4[k];
                uu[4*k+0] = t.x; uu[4*k+1] = t.y; uu[4*k+2] = t.z; uu[4*k+3] = t.w;
            }

            ull cb[4][10];
            #pragma unroll
            for (int qq = 0; qq < 4; qq++) {
                const int j = qq + (qq >= i ? 1 : 0);
                const float4* vq = reinterpret_cast<const float4*>(&s_v[gv + j * 20]);
                const float4* rq = reinterpret_cast<const float4*>(&s_rel[(i * 7 + qq) * 20]);
                #pragma unroll
                for (int k = 0; k < 5; k++) {
                    float4 vv = vq[k], rr = rq[k];
                    float x0 = fmaxf(uu[4*k+0] + vv.x, 0.0f) * rr.x;
                    float x1 = fmaxf(uu[4*k+1] + vv.y, 0.0f) * rr.y;
                    float x2 = fmaxf(uu[4*k+2] + vv.z, 0.0f) * rr.z;
                    float x3 = fmaxf(uu[4*k+3] + vv.w, 0.0f) * rr.w;
                    cb[qq][2*k+0] = f2pack(x0, x1);
                    cb[qq][2*k+1] = f2pack(x2, x3);
                }
            }

            #pragma unroll 1
            for (int o = 0; o < 20; o++) {
                const ulonglong2* w2 = reinterpret_cast<const ulonglong2*>(&s_hw[o][0]);
                ull h0 = s_hb2[o], h1 = h0, h2 = h0, h3 = h0;
                #pragma unroll
                for (int k = 0; k < 5; k++) {
                    ulonglong2 w = w2[k];
                    h0 = f2fma(w.x, cb[0][2*k+0], h0);
                    h1 = f2fma(w.x, cb[1][2*k+0], h1);
                    h2 = f2fma(w.x, cb[2][2*k+0], h2);
                    h3 = f2fma(w.x, cb[3][2*k+0], h3);
                    h0 = f2fma(w.y, cb[0][2*k+1], h0);
                    h1 = f2fma(w.y, cb[1][2*k+1], h1);
                    h2 = f2fma(w.y, cb[2][2*k+1], h2);
                    h3 = f2fma(w.y, cb[3][2*k+1], h3);
                }
                const float bw = s_bmw[o];
                acc = fmaf(bw, fmaxf(f2hadd(h0), 0.0f), acc);
                acc = fmaf(bw, fmaxf(f2hadd(h1), 0.0f), acc);
                acc = fmaf(bw, fmaxf(f2hadd(h2), 0.0f), acc);
                acc = fmaf(bw, fmaxf(f2hadd(h3), 0.0f), acc);
            }
        }

        // ----- chunk B: q = 4..6 -----
        {
            float uu[20];
            const float4* u4 = reinterpret_cast<const float4*>(&s_u[slot]);
            #pragma unroll
            for (int k = 0; k < 5; k++) {
                float4 t = u4[k];
                uu[4*k+0] = t.x; uu[4*k+1] = t.y; uu[4*k+2] = t.z; uu[4*k+3] = t.w;
            }

            ull cb[3][10];
            #pragma unroll
            for (int qq = 0; qq < 3; qq++) {
                const int q = 4 + qq;
                const int j = q + (q >= i ? 1 : 0);
                const float4* vq = reinterpret_cast<const float4*>(&s_v[gv + j * 20]);
                const float4* rq = reinterpret_cast<const float4*>(&s_rel[(i * 7 + q) * 20]);
                #pragma unroll
                for (int k = 0; k < 5; k++) {
                    float4 vv = vq[k], rr = rq[k];
                    float x0 = fmaxf(uu[4*k+0] + vv.x, 0.0f) * rr.x;
                    float x1 = fmaxf(uu[4*k+1] + vv.y, 0.0f) * rr.y;
                    float x2 = fmaxf(uu[4*k+2] + vv.z, 0.0f) * rr.z;
                    float x3 = fmaxf(uu[4*k+3] + vv.w, 0.0f) * rr.w;
                    cb[qq][2*k+0] = f2pack(x0, x1);
                    cb[qq][2*k+1] = f2pack(x2, x3);
                }
            }

            #pragma unroll 1
            for (int o = 0; o < 20; o++) {
                const ulonglong2* w2 = reinterpret_cast<const ulonglong2*>(&s_hw[o][0]);
                ull h0 = s_hb2[o], h1 = h0, h2 = h0;
                #pragma unroll
                for (int k = 0; k < 5; k++) {
                    ulonglong2 w = w2[k];
                    h0 = f2fma(w.x, cb[0][2*k+0], h0);
                    h1 = f2fma(w.x, cb[1][2*k+0], h1);
                    h2 = f2fma(w.x, cb[2][2*k+0], h2);
                    h0 = f2fma(w.y, cb[0][2*k+1], h0);
                    h1 = f2fma(w.y, cb[1][2*k+1], h1);
                    h2 = f2fma(w.y, cb[2][2*k+1], h2);
                }
                const float bw = s_bmw[o];
                acc = fmaf(bw, fmaxf(f2hadd(h0), 0.0f), acc);
                acc = fmaf(bw, fmaxf(f2hadd(h1), 0.0f), acc);
                acc = fmaf(bw, fmaxf(f2hadd(h2), 0.0f), acc);
            }
        }

        if (valid) out[b * 8 + i] = acc + bias7;

        __syncwarp();   // protect this warp's s_u/s_v slots before next tile's writes
    }
}

extern "C" void kernel_launch(void* const* d_in, const int* in_sizes, int n_in,
                              void* d_out, int out_size)
{
    const float* states      = (const float*)d_in[0];
    const int*   comp_mask   = (const int*)  d_in[1];
    const int*   phase_pairs = (const int*)  d_in[2];
    const float* p_w  = (const float*)d_in[3];
    const float* d_w  = (const float*)d_in[4];
    const float* d_b  = (const float*)d_in[5];
    const float* le_w = (const float*)d_in[6];
    const float* le_b = (const float*)d_in[7];
    const float* lc_w = (const float*)d_in[8];
    const float* lc_b = (const float*)d_in[9];
    const float* rel_w = (const float*)d_in[10];
    const float* rc_w  = (const float*)d_in[11];
    const float* rc_b  = (const float*)d_in[12];
    const float* h_w   = (const float*)d_in[13];
    const float* h_b   = (const float*)d_in[14];
    const float* bm_w  = (const float*)d_in[15];
    const float* bm_b  = (const float*)d_in[16];

    const int B = in_sizes[0] / 13;             // states is [B, 1 + 12]
    const int numTiles = (B + 15) / 16;
    const int blocks = numTiles < PERSIST_BLOCKS ? numTiles : PERSIST_BLOCKS;

    frap_kernel<<<blocks, 128>>>(states, comp_mask, phase_pairs,
                                 p_w, d_w, d_b, le_w, le_b, lc_w, lc_b,
                                 rel_w, rc_w, rc_b, h_w, h_b, bm_w, bm_b,
                                 (float*)d_out, B, numTiles);
}

// round 16
// speedup vs baseline: 1.2262x; 1.0338x over previous
#include <cuda_runtime.h>
#include <cstdint>

using ull = unsigned long long;

// ---------- packed f32x2 helpers (pack axis = channel c) ----------
__device__ __forceinline__ ull f2fma(ull a, ull b, ull c) {
    ull d; asm("fma.rn.f32x2 %0, %1, %2, %3;" : "=l"(d) : "l"(a), "l"(b), "l"(c)); return d;
}
__device__ __forceinline__ ull f2add(ull a, ull b) {
    ull d; asm("add.rn.f32x2 %0, %1, %2;" : "=l"(d) : "l"(a), "l"(b)); return d;
}
__device__ __forceinline__ ull f2mul(ull a, ull b) {
    ull d; asm("mul.rn.f32x2 %0, %1, %2;" : "=l"(d) : "l"(a), "l"(b)); return d;
}
// relu on both halves: 2x FMNMX on the ALU pipe (movs elide into register pairing)
__device__ __forceinline__ ull f2relu(ull p) {
    ull d;
    asm("{ .reg .f32 lo, hi;\n\t"
        "  mov.b64 {lo, hi}, %1;\n\t"
        "  max.f32 lo, lo, 0f00000000;\n\t"
        "  max.f32 hi, hi, 0f00000000;\n\t"
        "  mov.b64 %0, {lo, hi}; }" : "=l"(d) : "l"(p));
    return d;
}
__device__ __forceinline__ float f2hadd(ull p) {
    float a, b; asm("mov.b64 {%0, %1}, %2;" : "=f"(a), "=f"(b) : "l"(p));
    return a + b;
}
__device__ __forceinline__ ull f2pack(float a, float b) {
    ull r; asm("mov.b64 %0, {%1, %2};" : "=l"(r) : "f"(a), "f"(b)); return r;
}
__device__ __forceinline__ float sigm(float x) { return 1.0f / (1.0f + __expf(-x)); }

// u/v exchange layout (floats): addr = g*168 + phase*20 + c.
// 168 mod 32 = 8 -> 4 per-warp g-bases hit bank quads 0/8/16/24.
// v-exchange is INTRA-WARP -> __syncwarp() suffices at stage boundaries.
#define G_STRIDE 168
#define PERSIST_BLOCKS 592   // 148 SMs x 4 blocks/SM: all blocks resident

__global__ __launch_bounds__(128, 4)
void frap_kernel(const float* __restrict__ states,
                 const int*   __restrict__ comp_mask,
                 const int*   __restrict__ phase_pairs,
                 const float* __restrict__ p_w,
                 const float* __restrict__ d_w,  const float* __restrict__ d_b,
                 const float* __restrict__ le_w, const float* __restrict__ le_b,
                 const float* __restrict__ lc_w, const float* __restrict__ lc_b,
                 const float* __restrict__ rel_w,
                 const float* __restrict__ rc_w, const float* __restrict__ rc_b,
                 const float* __restrict__ h_w,  const float* __restrict__ h_b,
                 const float* __restrict__ bm_w, const float* __restrict__ bm_b,
                 float* __restrict__ out, int B, int numTiles)
{
    __shared__ __align__(16) float s_lcA[20][16];     // lc_w[:, 0:16]
    __shared__ __align__(16) float s_lcB[20][16];     // lc_w[:, 16:32]
    __shared__ __align__(16) float s_hw[20][20];      // natural c-pairs for f32x2
    __shared__ __align__(16) float s_rel[56 * 20];    // [i][q] compact
    __shared__ ull   s_leD2[4][8];                    // le_w[4+k][2cp..2cp+1] packed
    __shared__ ull   s_base2[2][8];                   // base[e][2cp..2cp+1] packed
    __shared__ float s_lcb[20], s_bmw[20], s_dw[4], s_db[4];
    __shared__ ull   s_bmw2[20];                      // (bm_w[o], bm_w[o]) splat
    __shared__ ull   s_hb2[20];                       // packed (h_b[o], 0)
    __shared__ int   s_pp[16];
    __shared__ float s_bmb;
    __shared__ __align__(16) float s_u[16 * G_STRIDE];
    __shared__ __align__(16) float s_v[16 * G_STRIDE];

    const int tid = threadIdx.x;

    // ---------------- precompute ONCE per persistent block ----------------
    for (int idx = tid; idx < 320; idx += 128) {
        int o = idx >> 4, c = idx & 15;
        s_lcA[o][c] = lc_w[o * 32 + c];
        s_lcB[o][c] = lc_w[o * 32 + 16 + c];
    }
    for (int idx = tid; idx < 400; idx += 128) {
        int o = idx / 20, c = idx % 20;
        s_hw[o][c] = h_w[o * 20 + c];
    }
    for (int idx = tid; idx < 1120; idx += 128) {
        int pq = idx / 20, o = idx % 20;
        int e = comp_mask[pq];
        float acc = rc_b[o];
        #pragma unroll
        for (int c4 = 0; c4 < 4; c4++)
            acc += fmaxf(rel_w[e * 4 + c4], 0.0f) * rc_w[o * 4 + c4];
        s_rel[pq * 20 + o] = fmaxf(acc, 0.0f);
    }
    if (tid < 32) {   // s_leD2[k][cp]
        int k = tid >> 3, cp = tid & 7;
        s_leD2[k][cp] = f2pack(le_w[(4 + k) * 16 + 2 * cp],
                               le_w[(4 + k) * 16 + 2 * cp + 1]);
    }
    if (tid < 16) {   // s_base2[e][cp]
        int e = tid >> 3, cp = tid & 7;
        float b0 = le_b[2 * cp], b1 = le_b[2 * cp + 1];
        #pragma unroll
        for (int k = 0; k < 4; k++) {
            float s = sigm(p_w[e * 4 + k]);
            b0 += s * le_w[k * 16 + 2 * cp];
            b1 += s * le_w[k * 16 + 2 * cp + 1];
        }
        s_base2[e][cp] = f2pack(b0, b1);
    }
    if (tid < 20) {
        s_lcb[tid]  = lc_b[tid];
        s_bmw[tid]  = bm_w[tid];
        s_bmw2[tid] = f2pack(bm_w[tid], bm_w[tid]);
        s_hb2[tid]  = f2pack(h_b[tid], 0.0f);
    }
    if (tid < 4) { s_dw[tid] = d_w[tid]; s_db[tid] = d_b[tid]; }
    if (tid >= 4 && tid < 20) s_pp[tid - 4] = phase_pairs[tid - 4];
    if (tid == 20) s_bmb = bm_b[0];
    __syncthreads();

    const int g = tid >> 3;
    const int i = tid & 7;
    const int mA = s_pp[i * 2], mB = s_pp[i * 2 + 1];
    const int slot = g * G_STRIDE + i * 20;
    const int gv = g * G_STRIDE;
    const float bias7 = 7.0f * s_bmb;

    // ---------------- persistent tile loop (warps decoupled) ----------------
    for (int tile = blockIdx.x; tile < numTiles; tile += gridDim.x) {
        const int b = tile * 16 + g;
        const bool valid = (b < B);
        const float* st = states + (valid ? b : 0) * 13;

        const int a  = (int)st[0];
        const int pa0 = s_pp[a * 2], pa1 = s_pp[a * 2 + 1];

        // ---------- stage 0: pairs (packed by c) ----------
        ull pairs2[8];
        #pragma unroll
        for (int cp = 0; cp < 8; cp++) pairs2[cp] = 0ULL;

        #pragma unroll
        for (int t = 0; t < 2; t++) {
            const int m = (t == 0) ? mA : mB;
            const float dm = st[1 + m];
            ull de2[4];
            #pragma unroll
            for (int k = 0; k < 4; k++) {
                float de = sigm(fmaf(dm, s_dw[k], s_db[k]));
                de2[k] = f2pack(de, de);
            }
            const int e = (m == pa0 || m == pa1) ? 1 : 0;
            #pragma unroll
            for (int cp = 0; cp < 8; cp++) {
                ull a2 = s_base2[e][cp];
                #pragma unroll
                for (int k = 0; k < 4; k++) a2 = f2fma(de2[k], s_leD2[k][cp], a2);
                pairs2[cp] = f2add(pairs2[cp], f2relu(a2));
            }
        }

        // ---------- stage 1: packed-by-c u/v matvec -> shared ----------
        {
            float4* u4p = reinterpret_cast<float4*>(&s_u[slot]);
            float4* v4p = reinterpret_cast<float4*>(&s_v[slot]);
            #pragma unroll 1
            for (int ob = 0; ob < 5; ob++) {
                float ur[4], vr[4];
                #pragma unroll
                for (int oi = 0; oi < 4; oi++) {
                    const int o = ob * 4 + oi;
                    const ulonglong2* wa = reinterpret_cast<const ulonglong2*>(&s_lcA[o][0]);
                    const ulonglong2* wb = reinterpret_cast<const ulonglong2*>(&s_lcB[o][0]);
                    ull au = 0ULL, av = 0ULL;
                    #pragma unroll
                    for (int k = 0; k < 4; k++) {
                        ulonglong2 A = wa[k], Bv = wb[k];
                        au = f2fma(A.x,  pairs2[2 * k + 0], au);
                        av = f2fma(Bv.x, pairs2[2 * k + 0], av);
                        au = f2fma(A.y,  pairs2[2 * k + 1], au);
                        av = f2fma(Bv.y, pairs2[2 * k + 1], av);
                    }
                    ur[oi] = f2hadd(au) + s_lcb[o];
                    vr[oi] = f2hadd(av);
                }
                u4p[ob] = make_float4(ur[0], ur[1], ur[2], ur[3]);
                v4p[ob] = make_float4(vr[0], vr[1], vr[2], vr[3]);
            }
        }
        __syncwarp();

        // ---------- stage 2: 7 real q's, chunked 4 + 3 ----------
        ull  acc2 = 0ULL;     // packed accumulator (chain pairs)
        float accs = 0.0f;    // scalar accumulator (odd chain of chunk B)

        // ----- chunk A: q = 0..3 -----
        {
            ull up[10];
            const ulonglong2* uu = reinterpret_cast<const ulonglong2*>(&s_u[slot]);
            #pragma unroll
            for (int k = 0; k < 5; k++) { ulonglong2 t = uu[k]; up[2*k] = t.x; up[2*k+1] = t.y; }

            ull cb[4][10];
            #pragma unroll
            for (int qq = 0; qq < 4; qq++) {
                const int j = qq + (qq >= i ? 1 : 0);
                const ulonglong2* vq = reinterpret_cast<const ulonglong2*>(&s_v[gv + j * 20]);
                const ulonglong2* rq = reinterpret_cast<const ulonglong2*>(&s_rel[(i * 7 + qq) * 20]);
                #pragma unroll
                for (int k = 0; k < 5; k++) {
                    ulonglong2 vv = vq[k], rr = rq[k];
                    cb[qq][2*k+0] = f2mul(f2relu(f2add(up[2*k+0], vv.x)), rr.x);
                    cb[qq][2*k+1] = f2mul(f2relu(f2add(up[2*k+1], vv.y)), rr.y);
                }
            }

            #pragma unroll 1
            for (int o = 0; o < 20; o++) {
                const ulonglong2* w2 = reinterpret_cast<const ulonglong2*>(&s_hw[o][0]);
                ull h0 = s_hb2[o], h1 = h0, h2 = h0, h3 = h0;
                #pragma unroll
                for (int k = 0; k < 5; k++) {
                    ulonglong2 w = w2[k];
                    h0 = f2fma(w.x, cb[0][2*k+0], h0);
                    h1 = f2fma(w.x, cb[1][2*k+0], h1);
                    h2 = f2fma(w.x, cb[2][2*k+0], h2);
                    h3 = f2fma(w.x, cb[3][2*k+0], h3);
                    h0 = f2fma(w.y, cb[0][2*k+1], h0);
                    h1 = f2fma(w.y, cb[1][2*k+1], h1);
                    h2 = f2fma(w.y, cb[2][2*k+1], h2);
                    h3 = f2fma(w.y, cb[3][2*k+1], h3);
                }
                // packed epilogue: 2 f2fma instead of 4 scalar fma
                ull r01 = f2pack(fmaxf(f2hadd(h0), 0.0f), fmaxf(f2hadd(h1), 0.0f));
                ull r23 = f2pack(fmaxf(f2hadd(h2), 0.0f), fmaxf(f2hadd(h3), 0.0f));
                acc2 = f2fma(s_bmw2[o], r01, acc2);
                acc2 = f2fma(s_bmw2[o], r23, acc2);
            }
        }

        // ----- chunk B: q = 4..6 -----
        {
            ull up[10];
            const ulonglong2* uu = reinterpret_cast<const ulonglong2*>(&s_u[slot]);
            #pragma unroll
            for (int k = 0; k < 5; k++) { ulonglong2 t = uu[k]; up[2*k] = t.x; up[2*k+1] = t.y; }

            ull cb[3][10];
            #pragma unroll
            for (int qq = 0; qq < 3; qq++) {
                const int q = 4 + qq;
                const int j = q + (q >= i ? 1 : 0);
                const ulonglong2* vq = reinterpret_cast<const ulonglong2*>(&s_v[gv + j * 20]);
                const ulonglong2* rq = reinterpret_cast<const ulonglong2*>(&s_rel[(i * 7 + q) * 20]);
                #pragma unroll
                for (int k = 0; k < 5; k++) {
                    ulonglong2 vv = vq[k], rr = rq[k];
                    cb[qq][2*k+0] = f2mul(f2relu(f2add(up[2*k+0], vv.x)), rr.x);
                    cb[qq][2*k+1] = f2mul(f2relu(f2add(up[2*k+1], vv.y)), rr.y);
                }
            }

            #pragma unroll 1
            for (int o = 0; o < 20; o++) {
                const ulonglong2* w2 = reinterpret_cast<const ulonglong2*>(&s_hw[o][0]);
                ull h0 = s_hb2[o], h1 = h0, h2 = h0;
                #pragma unroll
                for (int k = 0; k < 5; k++) {
                    ulonglong2 w = w2[k];
                    h0 = f2fma(w.x, cb[0][2*k+0], h0);
                    h1 = f2fma(w.x, cb[1][2*k+0], h1);
                    h2 = f2fma(w.x, cb[2][2*k+0], h2);
                    h0 = f2fma(w.y, cb[0][2*k+1], h0);
                    h1 = f2fma(w.y, cb[1][2*k+1], h1);
                    h2 = f2fma(w.y, cb[2][2*k+1], h2);
                }
                ull r01 = f2pack(fmaxf(f2hadd(h0), 0.0f), fmaxf(f2hadd(h1), 0.0f));
                acc2 = f2fma(s_bmw2[o], r01, acc2);
                accs = fmaf(s_bmw[o], fmaxf(f2hadd(h2), 0.0f), accs);
            }
        }

        if (valid) out[b * 8 + i] = f2hadd(acc2) + accs + bias7;

        __syncwarp();   // protect this warp's s_u/s_v before next tile
    }
}

extern "C" void kernel_launch(void* const* d_in, const int* in_sizes, int n_in,
                              void* d_out, int out_size)
{
    const float* states      = (const float*)d_in[0];
    const int*   comp_mask   = (const int*)  d_in[1];
    const int*   phase_pairs = (const int*)  d_in[2];
    const float* p_w  = (const float*)d_in[3];
    const float* d_w  = (const float*)d_in[4];
    const float* d_b  = (const float*)d_in[5];
    const float* le_w = (const float*)d_in[6];
    const float* le_b = (const float*)d_in[7];
    const float* lc_w = (const float*)d_in[8];
    const float* lc_b = (const float*)d_in[9];
    const float* rel_w = (const float*)d_in[10];
    const float* rc_w  = (const float*)d_in[11];
    const float* rc_b  = (const float*)d_in[12];
    const float* h_w   = (const float*)d_in[13];
    const float* h_b   = (const float*)d_in[14];
    const float* bm_w  = (const float*)d_in[15];
    const float* bm_b  = (const float*)d_in[16];

    const int B = in_sizes[0] / 13;             // states is [B, 1 + 12]
    const int numTiles = (B + 15) / 16;
    const int blocks = numTiles < PERSIST_BLOCKS ? numTiles : PERSIST_BLOCKS;

    frap_kernel<<<blocks, 128>>>(states, comp_mask, phase_pairs,
                                 p_w, d_w, d_b, le_w, le_b, lc_w, lc_b,
                                 rel_w, rc_w, rc_b, h_w, h_b, bm_w, bm_b,
                                 (float*)d_out, B, numTiles);
}